// round 9
// baseline (speedup 1.0000x reference)
#include <cuda_runtime.h>
#include <cuda_bf16.h>

// YOLOv1 loss: pred/target (BATCH, 14, 14, 30) fp32 -> scalar.
// S=14, B=2, C=20, LAMBDA_COORD=5, LAMBDA_NOOBJ=0.5, loss /= BATCH.
//
// HBM-bound streaming reduction:
//   kernel 1: grid-strided over 128-cell slabs; each slab's 2 x 15360B is
//             staged into smem via coalesced float4 streaming loads, per-cell
//             loss computed, block partial accumulated, one float per block
//             into a __device__ global array.
//   kernel 2: single block deterministically reduces the partials into d_out.

#define THREADS 128
#define ROW_PAD 31           // 30 -> 31 floats: conflict-free LDS (gcd(31,32)=1)
#define MAX_BLOCKS 16384

__device__ float g_partials[MAX_BLOCKS];

__device__ __forceinline__ float warp_reduce(float v) {
    #pragma unroll
    for (int off = 16; off > 0; off >>= 1)
        v += __shfl_down_sync(0xffffffffu, v, off);
    return v;
}

__device__ __forceinline__ float cell_loss(const float* __restrict__ p,
                                           const float* __restrict__ t) {
    const float invS = 1.0f / 14.0f;
    const bool obj = t[4] > 0.0f;

    const float tx = t[0], ty = t[1], tw = t[2], th = t[3];
    const float t_x0 = tx * invS - 0.5f * tw;
    const float t_y0 = ty * invS - 0.5f * th;
    const float t_x1 = tx * invS + 0.5f * tw;
    const float t_y1 = ty * invS + 0.5f * th;
    const float area_t = (t_x1 - t_x0) * (t_y1 - t_y0);

    float iou[2];
    #pragma unroll
    for (int b = 0; b < 2; b++) {
        const float px = p[5 * b + 0], py = p[5 * b + 1];
        const float pw = p[5 * b + 2], ph = p[5 * b + 3];
        const float px0 = px * invS - 0.5f * pw;
        const float py0 = py * invS - 0.5f * ph;
        const float px1 = px * invS + 0.5f * pw;
        const float py1 = py * invS + 0.5f * ph;
        const float ltx = fmaxf(px0, t_x0);
        const float lty = fmaxf(py0, t_y0);
        const float rbx = fminf(px1, t_x1);
        const float rby = fminf(py1, t_y1);
        const float wi = fmaxf(rbx - ltx, 0.0f);
        const float hi = fmaxf(rby - lty, 0.0f);
        const float inter  = wi * hi;
        const float area_p = (px1 - px0) * (py1 - py0);
        iou[b] = inter / (area_p + area_t - inter);
    }

    const int   r       = (iou[1] > iou[0]) ? 1 : 0;   // argmax, tie -> 0
    const float max_iou = (iou[1] > iou[0]) ? iou[1] : iou[0];

    if (obj) {
        const int rb = 5 * r;
        const float dx = p[rb + 0] - tx;
        const float dy = p[rb + 1] - ty;
        const float loss_xy = dx * dx + dy * dy;

        const float sw = sqrtf(p[rb + 2]) - sqrtf(tw);
        const float sh = sqrtf(p[rb + 3]) - sqrtf(th);
        const float loss_wh = sw * sw + sh * sh;

        const float dconf = p[rb + 4] - max_iou;
        const float loss_obj = dconf * dconf;

        float loss_cls = 0.0f;
        #pragma unroll
        for (int c = 0; c < 20; c++) {
            const float d = p[10 + c] - t[10 + c];
            loss_cls += d * d;
        }
        return 5.0f * (loss_xy + loss_wh) + loss_obj + loss_cls;
    } else {
        const float d0 = p[4] - t[4];
        const float d1 = p[9] - t[9];
        return 0.5f * (d0 * d0 + d1 * d1);
    }
}

__global__ void __launch_bounds__(THREADS)
yolo_loss_partial(const float* __restrict__ pred,
                  const float* __restrict__ target,
                  int n_cells, int n_slabs) {
    __shared__ float sp[THREADS * ROW_PAD];
    __shared__ float st[THREADS * ROW_PAD];

    const int tid = threadIdx.x;
    float blockAcc = 0.0f;

    for (int slab = blockIdx.x; slab < n_slabs; slab += gridDim.x) {
        const long long slabBase = (long long)slab * THREADS * 30;

        int cellsHere = n_cells - slab * THREADS;
        if (cellsHere > THREADS) cellsHere = THREADS;
        const int validFloats = cellsHere * 30;

        // ---- coalesced staged load: global (float4, streaming) -> smem ----
        const float4* __restrict__ pv = (const float4*)(pred + slabBase);
        const float4* __restrict__ tv = (const float4*)(target + slabBase);
        const int nvec = validFloats >> 2;
        for (int i = tid; i < nvec; i += THREADS) {
            float4 a = __ldcs(pv + i);
            float4 b = __ldcs(tv + i);
            int j = i << 2;
            #pragma unroll
            for (int k = 0; k < 4; k++) {
                int jj  = j + k;
                int row = jj / 30;
                int col = jj - row * 30;
                sp[row * ROW_PAD + col] = (&a.x)[k];
                st[row * ROW_PAD + col] = (&b.x)[k];
            }
        }
        for (int i = (nvec << 2) + tid; i < validFloats; i += THREADS) {   // tail
            int row = i / 30;
            int col = i - row * 30;
            sp[row * ROW_PAD + col] = __ldcs(pred + slabBase + i);
            st[row * ROW_PAD + col] = __ldcs(target + slabBase + i);
        }
        __syncthreads();

        // ---- per-cell loss ----
        if (tid < cellsHere)
            blockAcc += cell_loss(&sp[tid * ROW_PAD], &st[tid * ROW_PAD]);
        __syncthreads();   // protect smem before next slab's load
    }

    // ---- block reduction ----
    float v = warp_reduce(blockAcc);
    __shared__ float warpsum[THREADS / 32];
    const int lane = tid & 31;
    const int wid  = tid >> 5;
    if (lane == 0) warpsum[wid] = v;
    __syncthreads();
    if (tid == 0) {
        float s = 0.0f;
        #pragma unroll
        for (int w = 0; w < THREADS / 32; w++) s += warpsum[w];
        g_partials[blockIdx.x] = s;
    }
}

__global__ void __launch_bounds__(256)
yolo_loss_finalize(float* __restrict__ out, int nblocks, float inv_bs) {
    const int tid = threadIdx.x;
    float s = 0.0f;
    for (int i = tid; i < nblocks; i += 256)
        s += g_partials[i];
    s = warp_reduce(s);
    __shared__ float warpsum[8];
    const int lane = tid & 31;
    const int wid  = tid >> 5;
    if (lane == 0) warpsum[wid] = s;
    __syncthreads();
    if (tid == 0) {
        float total = 0.0f;
        #pragma unroll
        for (int w = 0; w < 8; w++) total += warpsum[w];
        out[0] = total * inv_bs;
    }
}

extern "C" void kernel_launch(void* const* d_in, const int* in_sizes, int n_in,
                              void* d_out, int out_size) {
    const float* pred   = (const float*)d_in[0];
    const float* target = (const float*)d_in[1];
    float* out = (float*)d_out;

    const int n       = in_sizes[0];
    const int n_cells = n / 30;                 // 802816 for the given shapes
    const int n_slabs = (n_cells + THREADS - 1) / THREADS;
    int blocks = n_slabs;
    if (blocks > MAX_BLOCKS) blocks = MAX_BLOCKS;  // grid-stride covers the rest

    // bs = n_cells / (S*S) = n_cells / 196 ; loss scaled by 1/bs
    const float inv_bs = 196.0f / (float)n_cells;

    yolo_loss_partial<<<blocks, THREADS>>>(pred, target, n_cells, n_slabs);
    yolo_loss_finalize<<<1, 256>>>(out, blocks, inv_bs);
}

// round 12
// speedup vs baseline: 1.0043x; 1.0043x over previous
#include <cuda_runtime.h>
#include <cuda_bf16.h>

// YOLOv1 loss: pred/target (BATCH, 14, 14, 30) fp32 -> scalar.
// Single persistent kernel: grid-strided slabs of 128 cells staged to smem,
// per-cell loss, per-block partial, last-block deterministic final reduction.

#define THREADS 128
#define ROW_PAD 31           // 30 -> 31 floats: conflict-free LDS (gcd(31,32)=1)
#define MAX_BLOCKS 2048      // >= 148 SM * 7 blocks/SM = 1036

__device__ float g_partials[MAX_BLOCKS];
__device__ unsigned int g_counter;   // zero at load; last block resets to 0

__device__ __forceinline__ float warp_reduce(float v) {
    #pragma unroll
    for (int off = 16; off > 0; off >>= 1)
        v += __shfl_down_sync(0xffffffffu, v, off);
    return v;
}

__device__ __forceinline__ float cell_loss(const float* __restrict__ p,
                                           const float* __restrict__ t) {
    const float invS = 1.0f / 14.0f;
    const bool obj = t[4] > 0.0f;

    const float tx = t[0], ty = t[1], tw = t[2], th = t[3];
    const float t_x0 = tx * invS - 0.5f * tw;
    const float t_y0 = ty * invS - 0.5f * th;
    const float t_x1 = tx * invS + 0.5f * tw;
    const float t_y1 = ty * invS + 0.5f * th;
    const float area_t = (t_x1 - t_x0) * (t_y1 - t_y0);

    float iou[2];
    #pragma unroll
    for (int b = 0; b < 2; b++) {
        const float px = p[5 * b + 0], py = p[5 * b + 1];
        const float pw = p[5 * b + 2], ph = p[5 * b + 3];
        const float px0 = px * invS - 0.5f * pw;
        const float py0 = py * invS - 0.5f * ph;
        const float px1 = px * invS + 0.5f * pw;
        const float py1 = py * invS + 0.5f * ph;
        const float ltx = fmaxf(px0, t_x0);
        const float lty = fmaxf(py0, t_y0);
        const float rbx = fminf(px1, t_x1);
        const float rby = fminf(py1, t_y1);
        const float wi = fmaxf(rbx - ltx, 0.0f);
        const float hi = fmaxf(rby - lty, 0.0f);
        const float inter  = wi * hi;
        const float area_p = (px1 - px0) * (py1 - py0);
        iou[b] = inter / (area_p + area_t - inter);
    }

    const int   r       = (iou[1] > iou[0]) ? 1 : 0;   // argmax, tie -> 0
    const float max_iou = (iou[1] > iou[0]) ? iou[1] : iou[0];

    if (obj) {
        const int rb = 5 * r;
        const float dx = p[rb + 0] - tx;
        const float dy = p[rb + 1] - ty;
        const float loss_xy = dx * dx + dy * dy;

        const float sw = sqrtf(p[rb + 2]) - sqrtf(tw);
        const float sh = sqrtf(p[rb + 3]) - sqrtf(th);
        const float loss_wh = sw * sw + sh * sh;

        const float dconf = p[rb + 4] - max_iou;
        const float loss_obj = dconf * dconf;

        float loss_cls = 0.0f;
        #pragma unroll
        for (int c = 0; c < 20; c++) {
            const float d = p[10 + c] - t[10 + c];
            loss_cls += d * d;
        }
        return 5.0f * (loss_xy + loss_wh) + loss_obj + loss_cls;
    } else {
        const float d0 = p[4] - t[4];
        const float d1 = p[9] - t[9];
        return 0.5f * (d0 * d0 + d1 * d1);
    }
}

__global__ void __launch_bounds__(THREADS)
yolo_loss_fused(const float* __restrict__ pred,
                const float* __restrict__ target,
                float* __restrict__ out,
                int n_cells, int n_slabs, float inv_bs) {
    __shared__ float sp[THREADS * ROW_PAD];
    __shared__ float st[THREADS * ROW_PAD];

    const int tid = threadIdx.x;
    float blockAcc = 0.0f;

    for (int slab = blockIdx.x; slab < n_slabs; slab += gridDim.x) {
        const long long slabBase = (long long)slab * THREADS * 30;

        int cellsHere = n_cells - slab * THREADS;
        if (cellsHere > THREADS) cellsHere = THREADS;
        const int validFloats = cellsHere * 30;

        // ---- coalesced staged load: global (float4, streaming) -> smem ----
        const float4* __restrict__ pv = (const float4*)(pred + slabBase);
        const float4* __restrict__ tv = (const float4*)(target + slabBase);
        const int nvec = validFloats >> 2;
        for (int i = tid; i < nvec; i += THREADS) {
            float4 a = __ldcs(pv + i);
            float4 b = __ldcs(tv + i);
            int j = i << 2;
            #pragma unroll
            for (int k = 0; k < 4; k++) {
                int jj  = j + k;
                int row = jj / 30;
                int col = jj - row * 30;
                sp[row * ROW_PAD + col] = (&a.x)[k];
                st[row * ROW_PAD + col] = (&b.x)[k];
            }
        }
        for (int i = (nvec << 2) + tid; i < validFloats; i += THREADS) {   // tail
            int row = i / 30;
            int col = i - row * 30;
            sp[row * ROW_PAD + col] = __ldcs(pred + slabBase + i);
            st[row * ROW_PAD + col] = __ldcs(target + slabBase + i);
        }
        __syncthreads();

        // ---- per-cell loss ----
        if (tid < cellsHere)
            blockAcc += cell_loss(&sp[tid * ROW_PAD], &st[tid * ROW_PAD]);
        __syncthreads();   // protect smem before next slab's load
    }

    // ---- block reduction -> partial ----
    float v = warp_reduce(blockAcc);
    __shared__ float warpsum[THREADS / 32];
    const int lane = tid & 31;
    const int wid  = tid >> 5;
    if (lane == 0) warpsum[wid] = v;
    __syncthreads();
    if (tid == 0) {
        float s = 0.0f;
        #pragma unroll
        for (int w = 0; w < THREADS / 32; w++) s += warpsum[w];
        g_partials[blockIdx.x] = s;
    }

    // ---- last-block deterministic final reduction ----
    __shared__ bool isLast;
    __threadfence();                 // make partial visible before counting
    if (tid == 0) {
        unsigned int prev = atomicAdd(&g_counter, 1u);
        isLast = (prev == gridDim.x - 1);
    }
    __syncthreads();
    if (isLast) {
        const int nb = gridDim.x;
        float s = 0.0f;
        for (int i = tid; i < nb; i += THREADS)   // fixed index order: deterministic
            s += g_partials[i];
        s = warp_reduce(s);
        if (lane == 0) warpsum[wid] = s;
        __syncthreads();
        if (tid == 0) {
            float total = 0.0f;
            #pragma unroll
            for (int w = 0; w < THREADS / 32; w++) total += warpsum[w];
            out[0] = total * inv_bs;
            g_counter = 0;           // reset for next graph replay
        }
    }
}

extern "C" void kernel_launch(void* const* d_in, const int* in_sizes, int n_in,
                              void* d_out, int out_size) {
    const float* pred   = (const float*)d_in[0];
    const float* target = (const float*)d_in[1];
    float* out = (float*)d_out;

    const int n       = in_sizes[0];
    const int n_cells = n / 30;                 // 802816 for the given shapes
    const int n_slabs = (n_cells + THREADS - 1) / THREADS;

    // persistent grid: one wave (~7 blocks/SM, smem-limited occupancy)
    int blocks = 148 * 7;
    if (blocks > n_slabs) blocks = n_slabs;
    if (blocks > MAX_BLOCKS) blocks = MAX_BLOCKS;

    // bs = n_cells / (S*S) = n_cells / 196 ; loss scaled by 1/bs
    const float inv_bs = 196.0f / (float)n_cells;

    yolo_loss_fused<<<blocks, THREADS>>>(pred, target, out, n_cells, n_slabs, inv_bs);
}